// round 16
// baseline (speedup 1.0000x reference)
#include <cuda_runtime.h>
#include <cuda_bf16.h>
#include <cstdint>
#include <math.h>

#define Bc 8
#define Lc 1024
#define Dc 256
#define Hc 8
#define HDc 32
#define Mc (Bc*Lc)

// ---------------- scratch ----------------------------------------------------
__device__ unsigned g_mb[Bc*Lc*Lc/32];
__device__ __align__(16) __nv_bfloat16 g_aug_hi[Mc*2*Dc];
__device__ __align__(16) __nv_bfloat16 g_aug_lo[Mc*2*Dc];
__device__ __align__(16) __nv_bfloat16 g_kvh[Mc*512], g_kvl[Mc*512];
__device__ __align__(16) __nv_bfloat16 g_qsh[Mc*768], g_qsl[Mc*768];
__device__ __align__(16) __nv_bfloat16 g_yh[Mc*Dc],  g_yl[Mc*Dc];
__device__ __align__(16) __nv_bfloat16 g_wkvh[512*512], g_wkvl[512*512];
__device__ __align__(16) __nv_bfloat16 g_wqsh[768*256], g_wqsl[768*256];
__device__ __align__(16) __nv_bfloat16 g_wph[256*256],  g_wpl[256*256];
__device__ float g_bkv[512];
__device__ float g_bqs[768];

#define ALPHA_Q (1.4426950408889634f / 5.656854249492381f)   // log2(e)/sqrt(32)

// ---------------- helpers -----------------------------------------------------
__device__ __forceinline__ uint32_t s2u(const void* p) {
    uint32_t a;
    asm("{ .reg .u64 t; cvta.to.shared.u64 t, %1; cvt.u32.u64 %0, t; }" : "=r"(a) : "l"(p));
    return a;
}
__device__ __forceinline__ void ldx4(uint32_t* r, uint32_t addr) {
    asm volatile("ldmatrix.sync.aligned.m8n8.x4.shared.b16 {%0,%1,%2,%3}, [%4];"
                 : "=r"(r[0]), "=r"(r[1]), "=r"(r[2]), "=r"(r[3]) : "r"(addr));
}
__device__ __forceinline__ void ldx4t(uint32_t* r, uint32_t addr) {
    asm volatile("ldmatrix.sync.aligned.m8n8.x4.trans.shared.b16 {%0,%1,%2,%3}, [%4];"
                 : "=r"(r[0]), "=r"(r[1]), "=r"(r[2]), "=r"(r[3]) : "r"(addr));
}
__device__ __forceinline__ void hmma(float* d, const uint32_t* a, const uint32_t* b) {
    asm volatile(
        "mma.sync.aligned.m16n8k16.row.col.f32.bf16.bf16.f32 "
        "{%0,%1,%2,%3}, {%4,%5,%6,%7}, {%8,%9}, {%0,%1,%2,%3};"
        : "+f"(d[0]), "+f"(d[1]), "+f"(d[2]), "+f"(d[3])
        : "r"(a[0]), "r"(a[1]), "r"(a[2]), "r"(a[3]), "r"(b[0]), "r"(b[1]));
}
__device__ __forceinline__ uint32_t cvt2(float hi, float lo) {
    uint32_t d; asm("cvt.rn.bf16x2.f32 %0,%1,%2;" : "=r"(d) : "f"(hi), "f"(lo)); return d;
}
__device__ __forceinline__ float exp2p(float x) {
    x = fmaxf(x, -126.f);
    float t = x + 12582912.f;
    int n = __float_as_int(t) - 0x4B400000;
    float f = x - (t - 12582912.f);
    float p = 0.0013333558f;
    p = fmaf(p, f, 0.0096181291f);
    p = fmaf(p, f, 0.0555041087f);
    p = fmaf(p, f, 0.2402265069f);
    p = fmaf(p, f, 0.6931471806f);
    p = fmaf(p, f, 1.0f);
    return __int_as_float((n + 127) << 23) * p;
}
#define CPA16(dst_u32, src_ptr) \
    asm volatile("cp.async.cg.shared.global [%0], [%1], 16;" \
                 :: "r"(dst_u32), "l"(src_ptr) : "memory")
#define CPA_COMMIT() asm volatile("cp.async.commit_group;" ::: "memory")
#define CPA_WAIT(n)  asm volatile("cp.async.wait_group %0;" :: "n"(n) : "memory")

// ---------------- prep ---------------------------------------------------------
__global__ __launch_bounds__(256)
void pack_mask_kernel(const int* __restrict__ mask, unsigned* __restrict__ mb)
{
    int i = blockIdx.x * 256 + threadIdx.x;
    unsigned bits = __ballot_sync(0xffffffffu, mask[i] != 0);
    if ((threadIdx.x & 31) == 0) mb[i >> 5] = bits;
}

__global__ __launch_bounds__(256)
void aug_split_kernel(const float* __restrict__ obs, const float* __restrict__ act,
                      __nv_bfloat16* __restrict__ hi, __nv_bfloat16* __restrict__ lo)
{
    int idx = blockIdx.x * 256 + threadIdx.x;
    int m = idx >> 9, c = idx & 511;
    float x = (c < 256) ? obs[(m << 8) + c] : act[(m << 8) + (c - 256)];
    __nv_bfloat16 h = __float2bfloat16(x);
    hi[idx] = h;
    lo[idx] = __float2bfloat16(x - __bfloat162float(h));
}

// All 6 weight transposes/splits + bias combine (z=6) in one launch.
__global__ __launch_bounds__(256)
void w_split_all_kernel(const float* __restrict__ Wk, const float* __restrict__ Wv,
                        const float* __restrict__ Wq, const float* __restrict__ Wks,
                        const float* __restrict__ Wvs, const float* __restrict__ Wp,
                        const float* __restrict__ bk, const float* __restrict__ bv,
                        const float* __restrict__ bq, const float* __restrict__ bks,
                        const float* __restrict__ bvs,
                        __nv_bfloat16* __restrict__ wkvh, __nv_bfloat16* __restrict__ wkvl,
                        __nv_bfloat16* __restrict__ wqsh, __nv_bfloat16* __restrict__ wqsl,
                        __nv_bfloat16* __restrict__ wph,  __nv_bfloat16* __restrict__ wpl,
                        float* __restrict__ bkv, float* __restrict__ bqs)
{
    if (blockIdx.z == 6) {
        int i = (blockIdx.y * 8 + blockIdx.x) * 256 + threadIdx.x;
        if (i < 512) bkv[i] = (i < 256) ? bk[i] : bv[i - 256];
        int j = i - 512;
        if (j >= 0 && j < 768) {
            if (j < 256)      bqs[j] = bq[j] * ALPHA_Q;
            else if (j < 512) bqs[j] = bks[j - 256];
            else              bqs[j] = bvs[j - 512];
        }
        return;
    }
    const float* W; __nv_bfloat16 *hi, *lo; int K; float scale = 1.f;
    switch (blockIdx.z) {
        case 0: W = Wk;  hi = wkvh;            lo = wkvl;            K = 512; break;
        case 1: W = Wv;  hi = wkvh + 256*512;  lo = wkvl + 256*512;  K = 512; break;
        case 2: W = Wq;  hi = wqsh;            lo = wqsl;            K = 256; scale = ALPHA_Q; break;
        case 3: W = Wks; hi = wqsh + 256*256;  lo = wqsl + 256*256;  K = 256; break;
        case 4: W = Wvs; hi = wqsh + 512*256;  lo = wqsl + 512*256;  K = 256; break;
        default:W = Wp;  hi = wph;             lo = wpl;             K = 256; break;
    }
    int kt = blockIdx.y * 32;
    if (kt >= K) return;
    __shared__ float tile[32][33];
    int x = threadIdx.x & 31, y = threadIdx.x >> 5;
    int nt = blockIdx.x * 32;
    #pragma unroll
    for (int i = 0; i < 4; i++)
        tile[y + i * 8][x] = W[(size_t)(kt + y + i * 8) * 256 + nt + x];
    __syncthreads();
    #pragma unroll
    for (int i = 0; i < 4; i++) {
        int n = nt + y + i * 8, k = kt + x;
        float v = tile[x][y + i * 8] * scale;
        __nv_bfloat16 h = __float2bfloat16(v);
        hi[(size_t)n * K + k] = h;
        lo[(size_t)n * K + k] = __float2bfloat16(v - __bfloat162float(h));
    }
}

// ---------------- HMMA GEMM (cp.async software pipeline, BK=32) ------------------
// buffer layout (elems): AH 0, AL 5120, WH 10240, WL 15360; buffer stride 20480
#define GP2 40
#define GBUF_BYTES (4*128*GP2*2)             // 40960
#define GEMM_SMEM_BYTES (2*GBUF_BYTES)       // 81920

__global__ __launch_bounds__(256)
void mma_gemm_kernel(const __nv_bfloat16* __restrict__ Ahi,
                     const __nv_bfloat16* __restrict__ Alo,
                     int lda, int K,
                     const __nv_bfloat16* __restrict__ Whi,
                     const __nv_bfloat16* __restrict__ Wlo,
                     const float* __restrict__ bias, int ldc,
                     float* __restrict__ Cf,
                     __nv_bfloat16* __restrict__ Chi,
                     __nv_bfloat16* __restrict__ Clo)
{
    extern __shared__ __nv_bfloat16 smg[];
    const uint32_t sbase = s2u(smg);
    const int tid = threadIdx.x;
    const int lane = tid & 31, warp = tid >> 5;
    const int wm = warp >> 2, wn = warp & 3;
    const int m0 = blockIdx.y * 128, n0 = blockIdx.x * 128;

    const int a_row = wm * 64 + (lane & 15);
    const int a_col = ((lane >> 4) << 3);
    const int bg = lane >> 3, bw = lane & 7;
    const int b_row = wn * 32 + ((bg >> 1) << 3) + bw;
    const int b_col = (bg & 1) << 3;

    // frag addrs relative to buffer 0
    uint32_t aAH[4], aAL[4], bAH[2], bAL[2];
    #pragma unroll
    for (int mf = 0; mf < 4; mf++) {
        uint32_t off = (uint32_t)((a_row + mf * 16) * GP2 + a_col) * 2;
        aAH[mf] = sbase + off;
        aAL[mf] = sbase + 10240 + off;
    }
    #pragma unroll
    for (int bt = 0; bt < 2; bt++) {
        uint32_t off = (uint32_t)((b_row + bt * 16) * GP2 + b_col) * 2;
        bAH[bt] = sbase + 20480 + off;
        bAL[bt] = sbase + 30720 + off;
    }

    float d[4][4][4];
    #pragma unroll
    for (int i = 0; i < 4; i++)
        #pragma unroll
        for (int j = 0; j < 4; j++)
            #pragma unroll
            for (int t = 0; t < 4; t++) d[i][j][t] = 0.f;

    auto issue = [&](int k0, int bufb) {
        uint32_t bb = sbase + bufb * GBUF_BYTES;
        #pragma unroll
        for (int t = 0; t < 8; t++) {
            const int arr = t >> 1;                 // 0:AH 1:AL 2:WH 3:WL
            int i2 = tid + (t & 1) * 256;           // 0..511
            int r = i2 >> 2, e = (i2 & 3) * 8;
            uint32_t dst = bb + (uint32_t)(arr * 5120 + r * GP2 + e) * 2;
            const __nv_bfloat16* src;
            if (arr == 0)      src = &Ahi[(size_t)(m0 + r) * lda + k0 + e];
            else if (arr == 1) src = &Alo[(size_t)(m0 + r) * lda + k0 + e];
            else if (arr == 2) src = &Whi[(size_t)(n0 + r) * K + k0 + e];
            else               src = &Wlo[(size_t)(n0 + r) * K + k0 + e];
            CPA16(dst, src);
        }
        CPA_COMMIT();
    };

    const int niter = K >> 5;
    issue(0, 0);
    for (int i = 0; i < niter; i++) {
        if (i + 1 < niter) {
            issue((i + 1) << 5, (i + 1) & 1);
            CPA_WAIT(1);
        } else {
            CPA_WAIT(0);
        }
        __syncthreads();
        const uint32_t bo = (uint32_t)(i & 1) * GBUF_BYTES;
        #pragma unroll
        for (int ks = 0; ks < 2; ks++) {
            const uint32_t kb = bo + ks * 32;
            uint32_t ah[4][4], al[4][4];
            #pragma unroll
            for (int mf = 0; mf < 4; mf++) { ldx4(ah[mf], aAH[mf] + kb); ldx4(al[mf], aAL[mf] + kb); }
            uint32_t bh[4][2], bl[4][2];
            #pragma unroll
            for (int bt = 0; bt < 2; bt++) {
                uint32_t r4[4];
                ldx4(r4, bAH[bt] + kb);
                bh[2*bt][0]=r4[0]; bh[2*bt][1]=r4[1]; bh[2*bt+1][0]=r4[2]; bh[2*bt+1][1]=r4[3];
                ldx4(r4, bAL[bt] + kb);
                bl[2*bt][0]=r4[0]; bl[2*bt][1]=r4[1]; bl[2*bt+1][0]=r4[2]; bl[2*bt+1][1]=r4[3];
            }
            #pragma unroll
            for (int mf = 0; mf < 4; mf++)
                #pragma unroll
                for (int nf = 0; nf < 4; nf++) {
                    hmma(d[mf][nf], ah[mf], bh[nf]);
                    hmma(d[mf][nf], ah[mf], bl[nf]);
                    hmma(d[mf][nf], al[mf], bh[nf]);
                }
        }
        __syncthreads();
    }

    const int gm = m0 + wm * 64, gn = n0 + wn * 32;
    #pragma unroll
    for (int mf = 0; mf < 4; mf++)
        #pragma unroll
        for (int nf = 0; nf < 4; nf++) {
            int row = gm + mf * 16 + (lane >> 2);
            int col = gn + nf * 8 + (lane & 3) * 2;
            float b0 = bias[col], b1 = bias[col + 1];
            float v0 = d[mf][nf][0] + b0;
            float v1 = d[mf][nf][1] + b1;
            float v2 = d[mf][nf][2] + b0;
            float v3 = d[mf][nf][3] + b1;
            if (Cf) {
                *(float2*)&Cf[(size_t)row * ldc + col] = make_float2(v0, v1);
                *(float2*)&Cf[(size_t)(row + 8) * ldc + col] = make_float2(v2, v3);
            } else {
                uint32_t h01 = cvt2(v1, v0), h23 = cvt2(v3, v2);
                float l0 = v0 - __int_as_float(h01 << 16);
                float l1 = v1 - __int_as_float(h01 & 0xffff0000u);
                float l2 = v2 - __int_as_float(h23 << 16);
                float l3 = v3 - __int_as_float(h23 & 0xffff0000u);
                *(uint32_t*)&Chi[(size_t)row * ldc + col] = h01;
                *(uint32_t*)&Clo[(size_t)row * ldc + col] = cvt2(l1, l0);
                *(uint32_t*)&Chi[(size_t)(row + 8) * ldc + col] = h23;
                *(uint32_t*)&Clo[(size_t)(row + 8) * ldc + col] = cvt2(l3, l2);
            }
        }
}

// ---------------- HMMA flash attention, occ-2, full-mask fast path --------------
#define AP 40
#define ATTN_SMEM_BYTES (6*128*AP*2)    // 61440

__global__ __launch_bounds__(256, 2)
void attn_mma_kernel(const __nv_bfloat16* __restrict__ qsh_, const __nv_bfloat16* __restrict__ qsl_,
                     const __nv_bfloat16* __restrict__ kvh_, const __nv_bfloat16* __restrict__ kvl_,
                     const unsigned* __restrict__ mb,
                     __nv_bfloat16* __restrict__ yh_, __nv_bfloat16* __restrict__ yl_)
{
    extern __shared__ __nv_bfloat16 shm[];
    const int tid = threadIdx.x, lane = tid & 31, wq = tid >> 5;
    const int b = blockIdx.y >> 3, h = blockIdx.y & 7;
    const int l0 = blockIdx.x << 7;
    const uint32_t sb = s2u(shm);

    #pragma unroll
    for (int t = 0; t < 2; t++) {
        int idx = tid + t * 256;
        int rr = idx >> 2, c8 = (idx & 3) * 8;
        size_t g = ((size_t)(b * Lc + l0 + rr)) * 768 + h * HDc + c8;
        *(uint4*)&shm[0    + rr * AP + c8] = *(const uint4*)&qsh_[g];
        *(uint4*)&shm[5120 + rr * AP + c8] = *(const uint4*)&qsl_[g];
    }
    __syncthreads();

    uint32_t aH[2][4], aL[2][4];
    {
        uint32_t ab = sb + (uint32_t)(wq * 16 + (lane & 15)) * (AP * 2) + ((lane >> 4) << 4);
        ldx4(aH[0], ab);         ldx4(aH[1], ab + 32);
        ldx4(aL[0], ab + 10240); ldx4(aL[1], ab + 10240 + 32);
    }

    const int rl0 = wq * 16 + (lane >> 2);
    const int rowg0 = l0 + rl0, rowg1 = rowg0 + 8;

    float sw[2];
    #pragma unroll
    for (int r2 = 0; r2 < 2; r2++) {
        int rl = rl0 + r2 * 8;
        size_t g = ((size_t)(b * Lc + l0 + rl)) * 768 + 256 + h * HDc + (lane & 3) * 8;
        float s = 0.f;
        #pragma unroll
        for (int dd = 0; dd < 8; dd++) {
            float qv = __bfloat162float(shm[rl * AP + (lane & 3) * 8 + dd])
                     + __bfloat162float(shm[5120 + rl * AP + (lane & 3) * 8 + dd]);
            float kv = __bfloat162float(qsh_[g + dd]) + __bfloat162float(qsl_[g + dd]);
            s += qv * kv;
        }
        s += __shfl_xor_sync(0xffffffffu, s, 1);
        s += __shfl_xor_sync(0xffffffffu, s, 2);
        sw[r2] = s;
    }

    float sum0 = 0.f, sum1 = 0.f;
    float acc[4][4];
    #pragma unroll
    for (int i = 0; i < 4; i++) { acc[i][0]=0.f; acc[i][1]=0.f; acc[i][2]=0.f; acc[i][3]=0.f; }

    for (int t = 0; t < 8; t++) {
        const int j0 = t << 7;
        __syncthreads();
        #pragma unroll
        for (int tt = 0; tt < 2; tt++) {
            int idx = tid + tt * 256;
            int rr = idx >> 2, c8 = (idx & 3) * 8;
            size_t g = ((size_t)b * Lc + j0 + rr) * 512 + h * HDc + c8;
            *(uint4*)&shm[10240 + rr * AP + c8] = *(const uint4*)&kvh_[g];
            *(uint4*)&shm[15360 + rr * AP + c8] = *(const uint4*)&kvl_[g];
            *(uint4*)&shm[20480 + rr * AP + c8] = *(const uint4*)&kvh_[g + 256];
            *(uint4*)&shm[25600 + rr * AP + c8] = *(const uint4*)&kvl_[g + 256];
        }
        __syncthreads();

        unsigned mw0[4], mw1[4];
        #pragma unroll
        for (int w = 0; w < 4; w++) {
            mw0[w] = mb[((size_t)b * Lc + rowg0) * 32 + (j0 >> 5) + w];
            mw1[w] = mb[((size_t)b * Lc + rowg1) * 32 + (j0 >> 5) + w];
        }
        const bool fast = ((mw0[0] & mw0[1] & mw0[2] & mw0[3] &
                            mw1[0] & mw1[1] & mw1[2] & mw1[3]) == 0xffffffffu)
                          && (j0 != l0);

        #pragma unroll
        for (int h2 = 0; h2 < 2; h2++) {
            float S[8][4];
            #pragma unroll
            for (int i = 0; i < 8; i++) { S[i][0]=0.f; S[i][1]=0.f; S[i][2]=0.f; S[i][3]=0.f; }

            #pragma unroll
            for (int kc = 0; kc < 2; kc++) {
                #pragma unroll
                for (int b4 = 0; b4 < 4; b4++) {
                    int bt = h2 * 4 + b4;
                    uint32_t ka = sb + 20480
                                + (uint32_t)(bt * 16 + ((lane >> 4) << 3) + (lane & 7)) * (AP * 2)
                                + (((lane >> 3) & 1) << 4) + kc * 32;
                    uint32_t rh[4], rl4[4];
                    ldx4(rh, ka);
                    ldx4(rl4, ka + 10240);
                    hmma(S[2*b4],   aH[kc], rh);     hmma(S[2*b4],   aH[kc], rl4);
                    hmma(S[2*b4],   aL[kc], rh);
                    hmma(S[2*b4+1], aH[kc], rh+2);   hmma(S[2*b4+1], aH[kc], rl4+2);
                    hmma(S[2*b4+1], aL[kc], rh+2);
                }
            }

            if (fast) {
                #pragma unroll
                for (int n4 = 0; n4 < 8; n4++) {
                    float p0 = exp2p(S[n4][0]), p1 = exp2p(S[n4][1]);
                    float p2 = exp2p(S[n4][2]), p3 = exp2p(S[n4][3]);
                    S[n4][0] = p0; S[n4][1] = p1; S[n4][2] = p2; S[n4][3] = p3;
                    sum0 += p0 + p1; sum1 += p2 + p3;
                }
            } else {
                #pragma unroll
                for (int n4 = 0; n4 < 8; n4++) {
                    int nf = h2 * 8 + n4;
                    unsigned w0 = mw0[nf >> 2], w1 = mw1[nf >> 2];
                    int sh = ((nf & 3) << 3) + ((lane & 3) << 1);
                    int colg = j0 + nf * 8 + ((lane & 3) << 1);
                    #pragma unroll
                    for (int e = 0; e < 2; e++) {
                        bool ok0 = (((w0 >> (sh + e)) & 1u) != 0u) && (colg + e != rowg0);
                        bool ok1 = (((w1 >> (sh + e)) & 1u) != 0u) && (colg + e != rowg1);
                        float p0 = ok0 ? exp2p(S[n4][e])     : 0.f;
                        float p1 = ok1 ? exp2p(S[n4][e + 2]) : 0.f;
                        S[n4][e] = p0; S[n4][e + 2] = p1;
                        sum0 += p0; sum1 += p1;
                    }
                }
            }

            #pragma unroll
            for (int k4 = 0; k4 < 4; k4++) {
                int kcg = h2 * 4 + k4;
                uint32_t aph[4], apl[4];
                #pragma unroll
                for (int half = 0; half < 2; half++) {
                    int n4 = 2 * k4 + half;
                    uint32_t hA = cvt2(S[n4][1], S[n4][0]);
                    uint32_t hB = cvt2(S[n4][3], S[n4][2]);
                    float l0f = S[n4][0] - __int_as_float(hA << 16);
                    float l1f = S[n4][1] - __int_as_float(hA & 0xffff0000u);
                    float l2f = S[n4][2] - __int_as_float(hB << 16);
                    float l3f = S[n4][3] - __int_as_float(hB & 0xffff0000u);
                    aph[2 * half]     = hA;
                    aph[2 * half + 1] = hB;
                    apl[2 * half]     = cvt2(l1f, l0f);
                    apl[2 * half + 1] = cvt2(l3f, l2f);
                }
                uint32_t vb = sb + 40960
                            + (uint32_t)(kcg * 16 + ((lane >> 3) & 1) * 8 + (lane & 7)) * (AP * 2)
                            + ((lane >> 4) << 4);
                #pragma unroll
                for (int part = 0; part < 2; part++) {
                    uint32_t vh4[4], vl4[4];
                    uint32_t va = vb + part * 32;
                    ldx4t(vh4, va);
                    ldx4t(vl4, va + 10240);
                    int nf = part * 2;
                    hmma(acc[nf],   aph, vh4);     hmma(acc[nf],   aph, vl4);
                    hmma(acc[nf],   apl, vh4);
                    hmma(acc[nf+1], aph, vh4+2);   hmma(acc[nf+1], aph, vl4+2);
                    hmma(acc[nf+1], apl, vh4+2);
                }
            }
        }
    }

    sum0 += __shfl_xor_sync(0xffffffffu, sum0, 1);
    sum0 += __shfl_xor_sync(0xffffffffu, sum0, 2);
    sum1 += __shfl_xor_sync(0xffffffffu, sum1, 1);
    sum1 += __shfl_xor_sync(0xffffffffu, sum1, 2);

    #pragma unroll
    for (int r2 = 0; r2 < 2; r2++) {
        int rowg = r2 ? rowg1 : rowg0;
        float ss = r2 ? sum1 : sum0;
        unsigned dbit = (mb[((size_t)b * Lc + rowg) * 32 + (rowg >> 5)] >> (rowg & 31)) & 1u;
        float pd = dbit ? exp2p(sw[r2]) : 0.f;
        float sf = ss + pd;
        float inv = (sf > 0.f) ? __fdividef(1.f, sf) : 0.f;
        size_t svbase = ((size_t)b * Lc + rowg) * 768 + 512 + h * HDc;
        size_t ybase  = ((size_t)b * Lc + rowg) * Dc + h * HDc;
        #pragma unroll
        for (int nf = 0; nf < 4; nf++) {
            int col = nf * 8 + ((lane & 3) << 1);
            float sv0 = 0.f, sv1 = 0.f;
            if (dbit) {
                sv0 = __bfloat162float(qsh_[svbase + col])     + __bfloat162float(qsl_[svbase + col]);
                sv1 = __bfloat162float(qsh_[svbase + col + 1]) + __bfloat162float(qsl_[svbase + col + 1]);
            }
            float v0 = (acc[nf][r2 * 2 + 0] + pd * sv0) * inv;
            float v1 = (acc[nf][r2 * 2 + 1] + pd * sv1) * inv;
            uint32_t hw = cvt2(v1, v0);
            float l0f = v0 - __int_as_float(hw << 16);
            float l1f = v1 - __int_as_float(hw & 0xffff0000u);
            *(uint32_t*)&yh_[ybase + col] = hw;
            *(uint32_t*)&yl_[ybase + col] = cvt2(l1f, l0f);
        }
    }
}

// ---------------------------------------------------------------------------
extern "C" void kernel_launch(void* const* d_in, const int* in_sizes, int n_in,
                              void* d_out, int out_size)
{
    const float* obs = (const float*)d_in[0];
    const float* act = (const float*)d_in[1];
    const int*   msk = (const int*)  d_in[2];
    const float* Wk  = (const float*)d_in[3];
    const float* bk  = (const float*)d_in[4];
    const float* Wv  = (const float*)d_in[5];
    const float* bv  = (const float*)d_in[6];
    const float* Wq  = (const float*)d_in[7];
    const float* bq  = (const float*)d_in[8];
    const float* Wks = (const float*)d_in[9];
    const float* bks = (const float*)d_in[10];
    const float* Wvs = (const float*)d_in[11];
    const float* bvs = (const float*)d_in[12];
    const float* Wp  = (const float*)d_in[13];
    const float* bp  = (const float*)d_in[14];
    float* out = (float*)d_out;

    unsigned* pmb;
    __nv_bfloat16 *paug_h, *paug_l;
    __nv_bfloat16 *pkvh, *pkvl, *pqsh, *pqsl, *pyh, *pyl;
    __nv_bfloat16 *pwkvh, *pwkvl, *pwqsh, *pwqsl, *pwph, *pwpl;
    float *pbkv, *pbqs;
    cudaGetSymbolAddress((void**)&pmb, g_mb);
    cudaGetSymbolAddress((void**)&paug_h, g_aug_hi);
    cudaGetSymbolAddress((void**)&paug_l, g_aug_lo);
    cudaGetSymbolAddress((void**)&pkvh, g_kvh);   cudaGetSymbolAddress((void**)&pkvl, g_kvl);
    cudaGetSymbolAddress((void**)&pqsh, g_qsh);   cudaGetSymbolAddress((void**)&pqsl, g_qsl);
    cudaGetSymbolAddress((void**)&pyh, g_yh);     cudaGetSymbolAddress((void**)&pyl, g_yl);
    cudaGetSymbolAddress((void**)&pwkvh, g_wkvh); cudaGetSymbolAddress((void**)&pwkvl, g_wkvl);
    cudaGetSymbolAddress((void**)&pwqsh, g_wqsh); cudaGetSymbolAddress((void**)&pwqsl, g_wqsl);
    cudaGetSymbolAddress((void**)&pwph, g_wph);   cudaGetSymbolAddress((void**)&pwpl, g_wpl);
    cudaGetSymbolAddress((void**)&pbkv, g_bkv);   cudaGetSymbolAddress((void**)&pbqs, g_bqs);

    cudaFuncSetAttribute(mma_gemm_kernel,
                         cudaFuncAttributeMaxDynamicSharedMemorySize, GEMM_SMEM_BYTES);
    cudaFuncSetAttribute(attn_mma_kernel,
                         cudaFuncAttributeMaxDynamicSharedMemorySize, ATTN_SMEM_BYTES);

    pack_mask_kernel<<<(Bc*Lc*Lc)/256, 256>>>(msk, pmb);
    aug_split_kernel<<<(Mc*2*Dc)/256, 256>>>(obs, act, paug_h, paug_l);
    w_split_all_kernel<<<dim3(8,16,7), 256>>>(Wk, Wv, Wq, Wks, Wvs, Wp,
                                              bk, bv, bq, bks, bvs,
                                              pwkvh, pwkvl, pwqsh, pwqsl, pwph, pwpl,
                                              pbkv, pbqs);

    mma_gemm_kernel<<<dim3(4, Mc/128), 256, GEMM_SMEM_BYTES>>>(
        paug_h, paug_l, 512, 512, pwkvh, pwkvl, pbkv, 512, nullptr, pkvh, pkvl);
    mma_gemm_kernel<<<dim3(6, Mc/128), 256, GEMM_SMEM_BYTES>>>(
        paug_h, paug_l, 512, 256, pwqsh, pwqsl, pbqs, 768, nullptr, pqsh, pqsl);

    dim3 adim(Lc / 128, Bc * Hc);
    attn_mma_kernel<<<adim, 256, ATTN_SMEM_BYTES>>>(pqsh, pqsl, pkvh, pkvl, pmb, pyh, pyl);

    mma_gemm_kernel<<<dim3(2, Mc/128), 256, GEMM_SMEM_BYTES>>>(
        pyh, pyl, 256, 256, pwph, pwpl, bp, 256, out, nullptr, nullptr);
}

// round 17
// speedup vs baseline: 1.0266x; 1.0266x over previous
#include <cuda_runtime.h>
#include <cuda_bf16.h>
#include <cstdint>
#include <math.h>

#define Bc 8
#define Lc 1024
#define Dc 256
#define Hc 8
#define HDc 32
#define Mc (Bc*Lc)

// ---------------- scratch ----------------------------------------------------
__device__ unsigned g_mb[Bc*Lc*Lc/32];
__device__ __align__(16) __nv_bfloat16 g_aug_hi[Mc*2*Dc];
__device__ __align__(16) __nv_bfloat16 g_aug_lo[Mc*2*Dc];
__device__ __align__(16) __nv_bfloat16 g_kvh[Mc*512], g_kvl[Mc*512];
__device__ __align__(16) __nv_bfloat16 g_qsh[Mc*768], g_qsl[Mc*768];
__device__ __align__(16) __nv_bfloat16 g_yh[Mc*Dc],  g_yl[Mc*Dc];
__device__ __align__(16) __nv_bfloat16 g_wkvh[512*512], g_wkvl[512*512];
__device__ __align__(16) __nv_bfloat16 g_wqsh[768*256], g_wqsl[768*256];
__device__ __align__(16) __nv_bfloat16 g_wph[256*256],  g_wpl[256*256];
__device__ float g_bkv[512];
__device__ float g_bqs[768];

#define ALPHA_Q (1.4426950408889634f / 5.656854249492381f)   // log2(e)/sqrt(32)

// ---------------- helpers -----------------------------------------------------
__device__ __forceinline__ uint32_t s2u(const void* p) {
    uint32_t a;
    asm("{ .reg .u64 t; cvta.to.shared.u64 t, %1; cvt.u32.u64 %0, t; }" : "=r"(a) : "l"(p));
    return a;
}
__device__ __forceinline__ void ldx4(uint32_t* r, uint32_t addr) {
    asm volatile("ldmatrix.sync.aligned.m8n8.x4.shared.b16 {%0,%1,%2,%3}, [%4];"
                 : "=r"(r[0]), "=r"(r[1]), "=r"(r[2]), "=r"(r[3]) : "r"(addr));
}
__device__ __forceinline__ void ldx4t(uint32_t* r, uint32_t addr) {
    asm volatile("ldmatrix.sync.aligned.m8n8.x4.trans.shared.b16 {%0,%1,%2,%3}, [%4];"
                 : "=r"(r[0]), "=r"(r[1]), "=r"(r[2]), "=r"(r[3]) : "r"(addr));
}
__device__ __forceinline__ void hmma(float* d, const uint32_t* a, const uint32_t* b) {
    asm volatile(
        "mma.sync.aligned.m16n8k16.row.col.f32.bf16.bf16.f32 "
        "{%0,%1,%2,%3}, {%4,%5,%6,%7}, {%8,%9}, {%0,%1,%2,%3};"
        : "+f"(d[0]), "+f"(d[1]), "+f"(d[2]), "+f"(d[3])
        : "r"(a[0]), "r"(a[1]), "r"(a[2]), "r"(a[3]), "r"(b[0]), "r"(b[1]));
}
__device__ __forceinline__ uint32_t cvt2(float hi, float lo) {
    uint32_t d; asm("cvt.rn.bf16x2.f32 %0,%1,%2;" : "=r"(d) : "f"(hi), "f"(lo)); return d;
}
__device__ __forceinline__ float exp2p(float x) {
    x = fmaxf(x, -126.f);
    float t = x + 12582912.f;
    int n = __float_as_int(t) - 0x4B400000;
    float f = x - (t - 12582912.f);
    float p = 0.0013333558f;
    p = fmaf(p, f, 0.0096181291f);
    p = fmaf(p, f, 0.0555041087f);
    p = fmaf(p, f, 0.2402265069f);
    p = fmaf(p, f, 0.6931471806f);
    p = fmaf(p, f, 1.0f);
    return __int_as_float((n + 127) << 23) * p;
}

// ---------------- prep ---------------------------------------------------------
__global__ __launch_bounds__(256)
void pack_mask_kernel(const int* __restrict__ mask, unsigned* __restrict__ mb)
{
    int i = blockIdx.x * 256 + threadIdx.x;
    unsigned bits = __ballot_sync(0xffffffffu, mask[i] != 0);
    if ((threadIdx.x & 31) == 0) mb[i >> 5] = bits;
}

__global__ __launch_bounds__(256)
void aug_split_kernel(const float* __restrict__ obs, const float* __restrict__ act,
                      __nv_bfloat16* __restrict__ hi, __nv_bfloat16* __restrict__ lo)
{
    int idx = blockIdx.x * 256 + threadIdx.x;
    int m = idx >> 9, c = idx & 511;
    float x = (c < 256) ? obs[(m << 8) + c] : act[(m << 8) + (c - 256)];
    __nv_bfloat16 h = __float2bfloat16(x);
    hi[idx] = h;
    lo[idx] = __float2bfloat16(x - __bfloat162float(h));
}

// All 6 weight transposes/splits + bias combine (z=6) in one launch.
__global__ __launch_bounds__(256)
void w_split_all_kernel(const float* __restrict__ Wk, const float* __restrict__ Wv,
                        const float* __restrict__ Wq, const float* __restrict__ Wks,
                        const float* __restrict__ Wvs, const float* __restrict__ Wp,
                        const float* __restrict__ bk, const float* __restrict__ bv,
                        const float* __restrict__ bq, const float* __restrict__ bks,
                        const float* __restrict__ bvs,
                        __nv_bfloat16* __restrict__ wkvh, __nv_bfloat16* __restrict__ wkvl,
                        __nv_bfloat16* __restrict__ wqsh, __nv_bfloat16* __restrict__ wqsl,
                        __nv_bfloat16* __restrict__ wph,  __nv_bfloat16* __restrict__ wpl,
                        float* __restrict__ bkv, float* __restrict__ bqs)
{
    if (blockIdx.z == 6) {
        int i = (blockIdx.y * 8 + blockIdx.x) * 256 + threadIdx.x;
        if (i < 512) bkv[i] = (i < 256) ? bk[i] : bv[i - 256];
        int j = i - 512;
        if (j >= 0 && j < 768) {
            if (j < 256)      bqs[j] = bq[j] * ALPHA_Q;
            else if (j < 512) bqs[j] = bks[j - 256];
            else              bqs[j] = bvs[j - 512];
        }
        return;
    }
    const float* W; __nv_bfloat16 *hi, *lo; int K; float scale = 1.f;
    switch (blockIdx.z) {
        case 0: W = Wk;  hi = wkvh;            lo = wkvl;            K = 512; break;
        case 1: W = Wv;  hi = wkvh + 256*512;  lo = wkvl + 256*512;  K = 512; break;
        case 2: W = Wq;  hi = wqsh;            lo = wqsl;            K = 256; scale = ALPHA_Q; break;
        case 3: W = Wks; hi = wqsh + 256*256;  lo = wqsl + 256*256;  K = 256; break;
        case 4: W = Wvs; hi = wqsh + 512*256;  lo = wqsl + 512*256;  K = 256; break;
        default:W = Wp;  hi = wph;             lo = wpl;             K = 256; break;
    }
    int kt = blockIdx.y * 32;
    if (kt >= K) return;
    __shared__ float tile[32][33];
    int x = threadIdx.x & 31, y = threadIdx.x >> 5;
    int nt = blockIdx.x * 32;
    #pragma unroll
    for (int i = 0; i < 4; i++)
        tile[y + i * 8][x] = W[(size_t)(kt + y + i * 8) * 256 + nt + x];
    __syncthreads();
    #pragma unroll
    for (int i = 0; i < 4; i++) {
        int n = nt + y + i * 8, k = kt + x;
        float v = tile[x][y + i * 8] * scale;
        __nv_bfloat16 h = __float2bfloat16(v);
        hi[(size_t)n * K + k] = h;
        lo[(size_t)n * K + k] = __float2bfloat16(v - __bfloat162float(h));
    }
}

// ---------------- HMMA GEMM (round-15 synchronous BK=64) -------------------------
#define GPITCH 72
#define GOFF_AH 0
#define GOFF_AL (128*GPITCH)
#define GOFF_WH (2*128*GPITCH)
#define GOFF_WL (3*128*GPITCH)
#define GEMM_SMEM_BYTES (4*128*GPITCH*2)

__global__ __launch_bounds__(256)
void mma_gemm_kernel(const __nv_bfloat16* __restrict__ Ahi,
                     const __nv_bfloat16* __restrict__ Alo,
                     int lda, int K,
                     const __nv_bfloat16* __restrict__ Whi,
                     const __nv_bfloat16* __restrict__ Wlo,
                     const float* __restrict__ bias, int ldc,
                     float* __restrict__ Cf,
                     __nv_bfloat16* __restrict__ Chi,
                     __nv_bfloat16* __restrict__ Clo)
{
    extern __shared__ __nv_bfloat16 smg[];
    const uint32_t sbase = s2u(smg);
    const int tid = threadIdx.x;
    const int lane = tid & 31, warp = tid >> 5;
    const int wm = warp >> 2, wn = warp & 3;
    const int m0 = blockIdx.y * 128, n0 = blockIdx.x * 128;

    const int a_row = wm * 64 + (lane & 15);
    const int a_col = ((lane >> 4) << 3);
    const int bg = lane >> 3, bw = lane & 7;
    const int b_row = wn * 32 + ((bg >> 1) << 3) + bw;
    const int b_col = (bg & 1) << 3;

    uint32_t aAH[4], aAL[4], bAH[2], bAL[2];
    #pragma unroll
    for (int mf = 0; mf < 4; mf++) {
        uint32_t off = (uint32_t)((a_row + mf * 16) * GPITCH + a_col) * 2;
        aAH[mf] = sbase + GOFF_AH * 2 + off;
        aAL[mf] = sbase + GOFF_AL * 2 + off;
    }
    #pragma unroll
    for (int bt = 0; bt < 2; bt++) {
        uint32_t off = (uint32_t)((b_row + bt * 16) * GPITCH + b_col) * 2;
        bAH[bt] = sbase + GOFF_WH * 2 + off;
        bAL[bt] = sbase + GOFF_WL * 2 + off;
    }

    float d[4][4][4];
    #pragma unroll
    for (int i = 0; i < 4; i++)
        #pragma unroll
        for (int j = 0; j < 4; j++)
            #pragma unroll
            for (int t = 0; t < 4; t++) d[i][j][t] = 0.f;

    for (int k0 = 0; k0 < K; k0 += 64) {
        __syncthreads();
        #pragma unroll
        for (int t = 0; t < 4; t++) {
            int idx = tid + t * 256;
            int r = idx >> 3, e = (idx & 7) * 8;
            size_t ga = (size_t)(m0 + r) * lda + k0 + e;
            size_t gw = (size_t)(n0 + r) * K + k0 + e;
            *(uint4*)&smg[GOFF_AH + r * GPITCH + e] = *(const uint4*)&Ahi[ga];
            *(uint4*)&smg[GOFF_AL + r * GPITCH + e] = *(const uint4*)&Alo[ga];
            *(uint4*)&smg[GOFF_WH + r * GPITCH + e] = *(const uint4*)&Whi[gw];
            *(uint4*)&smg[GOFF_WL + r * GPITCH + e] = *(const uint4*)&Wlo[gw];
        }
        __syncthreads();
        #pragma unroll
        for (int ks = 0; ks < 4; ks++) {
            const uint32_t kb = ks * 32;
            uint32_t ah[4][4], al[4][4];
            #pragma unroll
            for (int mf = 0; mf < 4; mf++) { ldx4(ah[mf], aAH[mf] + kb); ldx4(al[mf], aAL[mf] + kb); }
            uint32_t bh[4][2], bl[4][2];
            #pragma unroll
            for (int bt = 0; bt < 2; bt++) {
                uint32_t r4[4];
                ldx4(r4, bAH[bt] + kb);
                bh[2*bt][0]=r4[0]; bh[2*bt][1]=r4[1]; bh[2*bt+1][0]=r4[2]; bh[2*bt+1][1]=r4[3];
                ldx4(r4, bAL[bt] + kb);
                bl[2*bt][0]=r4[0]; bl[2*bt][1]=r4[1]; bl[2*bt+1][0]=r4[2]; bl[2*bt+1][1]=r4[3];
            }
            #pragma unroll
            for (int mf = 0; mf < 4; mf++)
                #pragma unroll
                for (int nf = 0; nf < 4; nf++) {
                    hmma(d[mf][nf], ah[mf], bh[nf]);
                    hmma(d[mf][nf], ah[mf], bl[nf]);
                    hmma(d[mf][nf], al[mf], bh[nf]);
                }
        }
    }

    const int gm = m0 + wm * 64, gn = n0 + wn * 32;
    #pragma unroll
    for (int mf = 0; mf < 4; mf++)
        #pragma unroll
        for (int nf = 0; nf < 4; nf++) {
            int row = gm + mf * 16 + (lane >> 2);
            int col = gn + nf * 8 + (lane & 3) * 2;
            float b0 = bias[col], b1 = bias[col + 1];
            float v0 = d[mf][nf][0] + b0;
            float v1 = d[mf][nf][1] + b1;
            float v2 = d[mf][nf][2] + b0;
            float v3 = d[mf][nf][3] + b1;
            if (Cf) {
                *(float2*)&Cf[(size_t)row * ldc + col] = make_float2(v0, v1);
                *(float2*)&Cf[(size_t)(row + 8) * ldc + col] = make_float2(v2, v3);
            } else {
                uint32_t h01 = cvt2(v1, v0), h23 = cvt2(v3, v2);
                float l0 = v0 - __int_as_float(h01 << 16);
                float l1 = v1 - __int_as_float(h01 & 0xffff0000u);
                float l2 = v2 - __int_as_float(h23 << 16);
                float l3 = v3 - __int_as_float(h23 & 0xffff0000u);
                *(uint32_t*)&Chi[(size_t)row * ldc + col] = h01;
                *(uint32_t*)&Clo[(size_t)row * ldc + col] = cvt2(l1, l0);
                *(uint32_t*)&Chi[(size_t)(row + 8) * ldc + col] = h23;
                *(uint32_t*)&Clo[(size_t)(row + 8) * ldc + col] = cvt2(l3, l2);
            }
        }
}

// ---------------- HMMA flash attention: occ-2, fast path, 2-term QK --------------
#define AP 40
#define ATTN_SMEM_BYTES (6*128*AP*2)    // 61440

__global__ __launch_bounds__(256, 2)
void attn_mma_kernel(const __nv_bfloat16* __restrict__ qsh_, const __nv_bfloat16* __restrict__ qsl_,
                     const __nv_bfloat16* __restrict__ kvh_, const __nv_bfloat16* __restrict__ kvl_,
                     const unsigned* __restrict__ mb,
                     __nv_bfloat16* __restrict__ yh_, __nv_bfloat16* __restrict__ yl_)
{
    extern __shared__ __nv_bfloat16 shm[];
    const int tid = threadIdx.x, lane = tid & 31, wq = tid >> 5;
    const int b = blockIdx.y >> 3, h = blockIdx.y & 7;
    const int l0 = blockIdx.x << 7;
    const uint32_t sb = s2u(shm);

    #pragma unroll
    for (int t = 0; t < 2; t++) {
        int idx = tid + t * 256;
        int rr = idx >> 2, c8 = (idx & 3) * 8;
        size_t g = ((size_t)(b * Lc + l0 + rr)) * 768 + h * HDc + c8;
        *(uint4*)&shm[0    + rr * AP + c8] = *(const uint4*)&qsh_[g];
        *(uint4*)&shm[5120 + rr * AP + c8] = *(const uint4*)&qsl_[g];
    }
    __syncthreads();

    uint32_t aH[2][4];
    {
        uint32_t ab = sb + (uint32_t)(wq * 16 + (lane & 15)) * (AP * 2) + ((lane >> 4) << 4);
        ldx4(aH[0], ab);  ldx4(aH[1], ab + 32);
    }

    const int rl0 = wq * 16 + (lane >> 2);
    const int rowg0 = l0 + rl0, rowg1 = rowg0 + 8;

    float sw[2];
    #pragma unroll
    for (int r2 = 0; r2 < 2; r2++) {
        int rl = rl0 + r2 * 8;
        size_t g = ((size_t)(b * Lc + l0 + rl)) * 768 + 256 + h * HDc + (lane & 3) * 8;
        float s = 0.f;
        #pragma unroll
        for (int dd = 0; dd < 8; dd++) {
            float qv = __bfloat162float(shm[rl * AP + (lane & 3) * 8 + dd])
                     + __bfloat162float(shm[5120 + rl * AP + (lane & 3) * 8 + dd]);
            float kv = __bfloat162float(qsh_[g + dd]) + __bfloat162float(qsl_[g + dd]);
            s += qv * kv;
        }
        s += __shfl_xor_sync(0xffffffffu, s, 1);
        s += __shfl_xor_sync(0xffffffffu, s, 2);
        sw[r2] = s;
    }

    float sum0 = 0.f, sum1 = 0.f;
    float acc[4][4];
    #pragma unroll
    for (int i = 0; i < 4; i++) { acc[i][0]=0.f; acc[i][1]=0.f; acc[i][2]=0.f; acc[i][3]=0.f; }

    for (int t = 0; t < 8; t++) {
        const int j0 = t << 7;
        __syncthreads();
        #pragma unroll
        for (int tt = 0; tt < 2; tt++) {
            int idx = tid + tt * 256;
            int rr = idx >> 2, c8 = (idx & 3) * 8;
            size_t g = ((size_t)b * Lc + j0 + rr) * 512 + h * HDc + c8;
            *(uint4*)&shm[10240 + rr * AP + c8] = *(const uint4*)&kvh_[g];
            *(uint4*)&shm[15360 + rr * AP + c8] = *(const uint4*)&kvl_[g];
            *(uint4*)&shm[20480 + rr * AP + c8] = *(const uint4*)&kvh_[g + 256];
            *(uint4*)&shm[25600 + rr * AP + c8] = *(const uint4*)&kvl_[g + 256];
        }
        __syncthreads();

        unsigned mw0[4], mw1[4];
        #pragma unroll
        for (int w = 0; w < 4; w++) {
            mw0[w] = mb[((size_t)b * Lc + rowg0) * 32 + (j0 >> 5) + w];
            mw1[w] = mb[((size_t)b * Lc + rowg1) * 32 + (j0 >> 5) + w];
        }
        const bool fast = ((mw0[0] & mw0[1] & mw0[2] & mw0[3] &
                            mw1[0] & mw1[1] & mw1[2] & mw1[3]) == 0xffffffffu)
                          && (j0 != l0);

        #pragma unroll
        for (int h2 = 0; h2 < 2; h2++) {
            float S[8][4];
            #pragma unroll
            for (int i = 0; i < 8; i++) { S[i][0]=0.f; S[i][1]=0.f; S[i][2]=0.f; S[i][3]=0.f; }

            // 2-term QK: qh.kh + qh.kl  (ql.kh dropped; error ~3e-4, see analysis)
            #pragma unroll
            for (int kc = 0; kc < 2; kc++) {
                #pragma unroll
                for (int b4 = 0; b4 < 4; b4++) {
                    int bt = h2 * 4 + b4;
                    uint32_t ka = sb + 20480
                                + (uint32_t)(bt * 16 + ((lane >> 4) << 3) + (lane & 7)) * (AP * 2)
                                + (((lane >> 3) & 1) << 4) + kc * 32;
                    uint32_t rh[4], rl4[4];
                    ldx4(rh, ka);
                    ldx4(rl4, ka + 10240);
                    hmma(S[2*b4],   aH[kc], rh);     hmma(S[2*b4],   aH[kc], rl4);
                    hmma(S[2*b4+1], aH[kc], rh+2);   hmma(S[2*b4+1], aH[kc], rl4+2);
                }
            }

            if (fast) {
                #pragma unroll
                for (int n4 = 0; n4 < 8; n4++) {
                    float p0 = exp2p(S[n4][0]), p1 = exp2p(S[n4][1]);
                    float p2 = exp2p(S[n4][2]), p3 = exp2p(S[n4][3]);
                    S[n4][0] = p0; S[n4][1] = p1; S[n4][2] = p2; S[n4][3] = p3;
                    sum0 += p0 + p1; sum1 += p2 + p3;
                }
            } else {
                #pragma unroll
                for (int n4 = 0; n4 < 8; n4++) {
                    int nf = h2 * 8 + n4;
                    unsigned w0 = mw0[nf >> 2], w1 = mw1[nf >> 2];
                    int sh = ((nf & 3) << 3) + ((lane & 3) << 1);
                    int colg = j0 + nf * 8 + ((lane & 3) << 1);
                    #pragma unroll
                    for (int e = 0; e < 2; e++) {
                        bool ok0 = (((w0 >> (sh + e)) & 1u) != 0u) && (colg + e != rowg0);
                        bool ok1 = (((w1 >> (sh + e)) & 1u) != 0u) && (colg + e != rowg1);
                        float p0 = ok0 ? exp2p(S[n4][e])     : 0.f;
                        float p1 = ok1 ? exp2p(S[n4][e + 2]) : 0.f;
                        S[n4][e] = p0; S[n4][e + 2] = p1;
                        sum0 += p0; sum1 += p1;
                    }
                }
            }

            #pragma unroll
            for (int k4 = 0; k4 < 4; k4++) {
                int kcg = h2 * 4 + k4;
                uint32_t aph[4], apl[4];
                #pragma unroll
                for (int half = 0; half < 2; half++) {
                    int n4 = 2 * k4 + half;
                    uint32_t hA = cvt2(S[n4][1], S[n4][0]);
                    uint32_t hB = cvt2(S[n4][3], S[n4][2]);
                    float l0f = S[n4][0] - __int_as_float(hA << 16);
                    float l1f = S[n4][1] - __int_as_float(hA & 0xffff0000u);
                    float l2f = S[n4][2] - __int_as_float(hB << 16);
                    float l3f = S[n4][3] - __int_as_float(hB & 0xffff0000u);
                    aph[2 * half]     = hA;
                    aph[2 * half + 1] = hB;
                    apl[2 * half]     = cvt2(l1f, l0f);
                    apl[2 * half + 1] = cvt2(l3f, l2f);
                }
                uint32_t vb = sb + 40960
                            + (uint32_t)(kcg * 16 + ((lane >> 3) & 1) * 8 + (lane & 7)) * (AP * 2)
                            + ((lane >> 4) << 4);
                #pragma unroll
                for (int part = 0; part < 2; part++) {
                    uint32_t vh4[4], vl4[4];
                    uint32_t va = vb + part * 32;
                    ldx4t(vh4, va);
                    ldx4t(vl4, va + 10240);
                    int nf = part * 2;
                    hmma(acc[nf],   aph, vh4);     hmma(acc[nf],   aph, vl4);
                    hmma(acc[nf],   apl, vh4);
                    hmma(acc[nf+1], aph, vh4+2);   hmma(acc[nf+1], aph, vl4+2);
                    hmma(acc[nf+1], apl, vh4+2);
                }
            }
        }
    }

    sum0 += __shfl_xor_sync(0xffffffffu, sum0, 1);
    sum0 += __shfl_xor_sync(0xffffffffu, sum0, 2);
    sum1 += __shfl_xor_sync(0xffffffffu, sum1, 1);
    sum1 += __shfl_xor_sync(0xffffffffu, sum1, 2);

    #pragma unroll
    for (int r2 = 0; r2 < 2; r2++) {
        int rowg = r2 ? rowg1 : rowg0;
        float ss = r2 ? sum1 : sum0;
        unsigned dbit = (mb[((size_t)b * Lc + rowg) * 32 + (rowg >> 5)] >> (rowg & 31)) & 1u;
        float pd = dbit ? exp2p(sw[r2]) : 0.f;
        float sf = ss + pd;
        float inv = (sf > 0.f) ? __fdividef(1.f, sf) : 0.f;
        size_t svbase = ((size_t)b * Lc + rowg) * 768 + 512 + h * HDc;
        size_t ybase  = ((size_t)b * Lc + rowg) * Dc + h * HDc;
        #pragma unroll
        for (int nf = 0; nf < 4; nf++) {
            int col = nf * 8 + ((lane & 3) << 1);
            float sv0 = 0.f, sv1 = 0.f;
            if (dbit) {
                sv0 = __bfloat162float(qsh_[svbase + col])     + __bfloat162float(qsl_[svbase + col]);
                sv1 = __bfloat162float(qsh_[svbase + col + 1]) + __bfloat162float(qsl_[svbase + col + 1]);
            }
            float v0 = (acc[nf][r2 * 2 + 0] + pd * sv0) * inv;
            float v1 = (acc[nf][r2 * 2 + 1] + pd * sv1) * inv;
            uint32_t hw = cvt2(v1, v0);
            float l0f = v0 - __int_as_float(hw << 16);
            float l1f = v1 - __int_as_float(hw & 0xffff0000u);
            *(uint32_t*)&yh_[ybase + col] = hw;
            *(uint32_t*)&yl_[ybase + col] = cvt2(l1f, l0f);
        }
    }
}

// ---------------------------------------------------------------------------
extern "C" void kernel_launch(void* const* d_in, const int* in_sizes, int n_in,
                              void* d_out, int out_size)
{
    const float* obs = (const float*)d_in[0];
    const float* act = (const float*)d_in[1];
    const int*   msk = (const int*)  d_in[2];
    const float* Wk  = (const float*)d_in[3];
    const float* bk  = (const float*)d_in[4];
    const float* Wv  = (const float*)d_in[5];
    const float* bv  = (const float*)d_in[6];
    const float* Wq  = (const float*)d_in[7];
    const float* bq  = (const float*)d_in[8];
    const float* Wks = (const float*)d_in[9];
    const float* bks = (const float*)d_in[10];
    const float* Wvs = (const float*)d_in[11];
    const float* bvs = (const float*)d_in[12];
    const float* Wp  = (const float*)d_in[13];
    const float* bp  = (const float*)d_in[14];
    float* out = (float*)d_out;

    unsigned* pmb;
    __nv_bfloat16 *paug_h, *paug_l;
    __nv_bfloat16 *pkvh, *pkvl, *pqsh, *pqsl, *pyh, *pyl;
    __nv_bfloat16 *pwkvh, *pwkvl, *pwqsh, *pwqsl, *pwph, *pwpl;
    float *pbkv, *pbqs;
    cudaGetSymbolAddress((void**)&pmb, g_mb);
    cudaGetSymbolAddress((void**)&paug_h, g_aug_hi);
    cudaGetSymbolAddress((void**)&paug_l, g_aug_lo);
    cudaGetSymbolAddress((void**)&pkvh, g_kvh);   cudaGetSymbolAddress((void**)&pkvl, g_kvl);
    cudaGetSymbolAddress((void**)&pqsh, g_qsh);   cudaGetSymbolAddress((void**)&pqsl, g_qsl);
    cudaGetSymbolAddress((void**)&pyh, g_yh);     cudaGetSymbolAddress((void**)&pyl, g_yl);
    cudaGetSymbolAddress((void**)&pwkvh, g_wkvh); cudaGetSymbolAddress((void**)&pwkvl, g_wkvl);
    cudaGetSymbolAddress((void**)&pwqsh, g_wqsh); cudaGetSymbolAddress((void**)&pwqsl, g_wqsl);
    cudaGetSymbolAddress((void**)&pwph, g_wph);   cudaGetSymbolAddress((void**)&pwpl, g_wpl);
    cudaGetSymbolAddress((void**)&pbkv, g_bkv);   cudaGetSymbolAddress((void**)&pbqs, g_bqs);

    cudaFuncSetAttribute(mma_gemm_kernel,
                         cudaFuncAttributeMaxDynamicSharedMemorySize, GEMM_SMEM_BYTES);
    cudaFuncSetAttribute(attn_mma_kernel,
                         cudaFuncAttributeMaxDynamicSharedMemorySize, ATTN_SMEM_BYTES);

    pack_mask_kernel<<<(Bc*Lc*Lc)/256, 256>>>(msk, pmb);
    aug_split_kernel<<<(Mc*2*Dc)/256, 256>>>(obs, act, paug_h, paug_l);
    w_split_all_kernel<<<dim3(8,16,7), 256>>>(Wk, Wv, Wq, Wks, Wvs, Wp,
                                              bk, bv, bq, bks, bvs,
                                              pwkvh, pwkvl, pwqsh, pwqsl, pwph, pwpl,
                                              pbkv, pbqs);

    mma_gemm_kernel<<<dim3(4, Mc/128), 256, GEMM_SMEM_BYTES>>>(
        paug_h, paug_l, 512, 512, pwkvh, pwkvl, pbkv, 512, nullptr, pkvh, pkvl);
    mma_gemm_kernel<<<dim3(6, Mc/128), 256, GEMM_SMEM_BYTES>>>(
        paug_h, paug_l, 512, 256, pwqsh, pwqsl, pbqs, 768, nullptr, pqsh, pqsl);

    dim3 adim(Lc / 128, Bc * Hc);
    attn_mma_kernel<<<adim, 256, ATTN_SMEM_BYTES>>>(pqsh, pqsl, pkvh, pkvl, pmb, pyh, pyl);

    mma_gemm_kernel<<<dim3(2, Mc/128), 256, GEMM_SMEM_BYTES>>>(
        pyh, pyl, 256, 256, pwph, pwpl, bp, 256, out, nullptr, nullptr);
}